// round 14
// baseline (speedup 1.0000x reference)
#include <cuda_runtime.h>
#include <math.h>

#define BB 256
#define NCH 32
#define TT 2000
#define NTF 4
#define NSF 40
#define NSUB 20
#define TK 25
#define NPAIR 210
#define NCHUNK 8
#define TC 250
#define ZW 280
#define YSS 258
#define NSWEEP 5

typedef unsigned long long ull;

__device__ float g_W2D[32 * 160];              // [c*160 + 2*sg], duplicated
__device__ float g_part[NCHUNK][BB][420];

__device__ __forceinline__ void fma2(ull& d, ull a, ull b) {
    asm("fma.rn.f32x2 %0, %1, %2, %0;" : "+l"(d) : "l"(a), "l"(b));
}
__device__ __forceinline__ ull pack2(float lo, float hi) {
    ull r; asm("mov.b64 %0, {%1, %2};" : "=l"(r) : "f"(lo), "f"(hi)); return r;
}
__device__ __forceinline__ float2 unpack2(ull v) {
    float2 f; asm("mov.b64 {%0, %1}, %2;" : "=f"(f.x), "=f"(f.y) : "l"(v)); return f;
}

// ---------------------------------------------------------------------------
__global__ void prep_kernel(const float* __restrict__ conv2_w,
                            const float* __restrict__ W_bimap) {
    int idx = blockIdx.x * blockDim.x + threadIdx.x;
    if (idx < 2560) {
        int c = idx / 80, sg = idx % 80;
        int s = sg / 4, g = sg % 4;
        float acc = 0.f;
        #pragma unroll 8
        for (int f = 0; f < NSF; ++f)
            acc += W_bimap[s * NSF + f] * conv2_w[f * 128 + g * 32 + c];
        g_W2D[c * 160 + 2 * sg]     = acc;
        g_W2D[c * 160 + 2 * sg + 1] = acc;
    }
}

// ---------------------------------------------------------------------------
// Fused pipeline: warps 0-3 produce z slab n+1 (GEMM) while warps 4-7 consume
// slab n (temporal conv -> ys, zero-padding t>=250 inline). Then covariance.
// ---------------------------------------------------------------------------
__global__ void __launch_bounds__(256)
fused_kernel(const float* __restrict__ x, const float* __restrict__ w1) {
    extern __shared__ float smem[];
    float* xs  = smem;                  // 32*280 = 8960
    float* zs0 = xs + 32 * ZW;          // 4480
    float* zs1 = zs0 + 16 * ZW;         // 4480
    float* ys  = zs1 + 16 * ZW;         // 5160
    float* w2d = ys + 20 * YSS;         // 5120 (duplicated)
    float* w1p = w2d + 5120;            // 224
    float* red = zs0;                   // cov reduction aliases zs0

    const int tid = threadIdx.x;
    const int chunk = blockIdx.x, b = blockIdx.y;
    const int t0 = chunk * TC;
    const float* __restrict__ xb = x + (size_t)b * NCH * TT;

    for (int idx = tid; idx < 32 * ZW; idx += 256) {
        int c = idx / ZW, tt = idx % ZW;
        int gi = t0 - 12 + tt;
        if (gi < 0) gi = -gi;
        if (gi >= TT) gi = 2 * TT - 2 - gi;
        xs[c * ZW + tt] = xb[c * TT + gi];
    }
    for (int idx = tid; idx < 5120; idx += 256) w2d[idx] = g_W2D[idx];
    if (tid < 104) {
        int phase = tid / 52, rem = tid % 52, g = rem / 13, i = rem % 13;
        float lo, hi;
        if (phase == 0) {
            lo = w1[g * TK + 2 * i];
            hi = (i < 12) ? w1[g * TK + 2 * i + 1] : 0.f;
        } else {
            lo = (i == 0) ? 0.f : w1[g * TK + 2 * i - 1];
            hi = w1[g * TK + 2 * i];
        }
        int base = (phase * 4 + g) * 28 + 2 * i;
        w1p[base] = lo; w1p[base + 1] = hi;
    }
    if (tid >= 104 && tid < 120) {
        int s = tid - 104;
        w1p[(s >> 1) * 28 + 26 + (s & 1)] = 0.f;
    }
    __syncthreads();

    const int warp = tid >> 5, lane = tid & 31;
    const ull* wp = (const ull*)w1p;

    auto produceA = [&](int slb, float* zbuf) {
        if (lane >= 28) return;
        const int tau0 = lane * 10;
        const int sg0 = (slb * 4 + warp) * 4;
        ull acc[4][5];
        #pragma unroll
        for (int q = 0; q < 4; ++q)
            #pragma unroll
            for (int p = 0; p < 5; ++p) acc[q][p] = 0;

        #pragma unroll 2
        for (int c = 0; c < NCH; ++c) {
            const ull* xp = (const ull*)&xs[c * ZW + tau0];
            ull xv0 = xp[0], xv1 = xp[1], xv2 = xp[2], xv3 = xp[3], xv4 = xp[4];
            const ull* wdp = (const ull*)&w2d[c * 160 + 2 * sg0];  // broadcast
            ull wd0 = wdp[0], wd1 = wdp[1], wd2 = wdp[2], wd3 = wdp[3];
            fma2(acc[0][0], xv0, wd0); fma2(acc[0][1], xv1, wd0);
            fma2(acc[0][2], xv2, wd0); fma2(acc[0][3], xv3, wd0);
            fma2(acc[0][4], xv4, wd0);
            fma2(acc[1][0], xv0, wd1); fma2(acc[1][1], xv1, wd1);
            fma2(acc[1][2], xv2, wd1); fma2(acc[1][3], xv3, wd1);
            fma2(acc[1][4], xv4, wd1);
            fma2(acc[2][0], xv0, wd2); fma2(acc[2][1], xv1, wd2);
            fma2(acc[2][2], xv2, wd2); fma2(acc[2][3], xv3, wd2);
            fma2(acc[2][4], xv4, wd2);
            fma2(acc[3][0], xv0, wd3); fma2(acc[3][1], xv1, wd3);
            fma2(acc[3][2], xv2, wd3); fma2(acc[3][3], xv3, wd3);
            fma2(acc[3][4], xv4, wd3);
        }
        #pragma unroll
        for (int q = 0; q < 4; ++q) {
            ull* zr = (ull*)&zbuf[(warp * 4 + q) * ZW + tau0];
            #pragma unroll
            for (int p = 0; p < 5; ++p) zr[p] = acc[q][p];
        }
    };

    auto consumeB = [&](int slb, const float* zbuf) {
        const int s_loc = warp - 4;
        const int tl = lane * 8;
        ull accP[8];
        #pragma unroll
        for (int o = 0; o < 8; ++o) accP[o] = 0;

        #pragma unroll
        for (int g = 0; g < 4; ++g) {
            const ull* zrow = (const ull*)&zbuf[(s_loc * 4 + g) * ZW + tl];
            ull win[16];
            #pragma unroll
            for (int j = 0; j < 16; ++j) win[j] = zrow[j];
            #pragma unroll
            for (int i = 0; i < 13; ++i) {
                ull wa = wp[g * 14 + i], wb = wp[(4 + g) * 14 + i];
                #pragma unroll
                for (int m = 0; m < 4; ++m) {
                    fma2(accP[2 * m],     win[m + i], wa);
                    fma2(accP[2 * m + 1], win[m + i], wb);
                }
            }
        }
        const int s = slb * 4 + s_loc;
        // y for t >= TC zeroed inline; float2 stores (8B-aligned for all s)
        #pragma unroll
        for (int m = 0; m < 4; ++m) {
            float2 e = unpack2(accP[2 * m]);
            float2 o = unpack2(accP[2 * m + 1]);
            bool ok = (tl + 2 * m) < TC;
            float lo = ok ? (e.x + e.y) : 0.f;
            float hi = ok ? (o.x + o.y) : 0.f;
            *(float2*)&ys[s * YSS + tl + 2 * m] = make_float2(lo, hi);
        }
    };

    if (warp < 4) produceA(0, zs0);
    __syncthreads();
    #pragma unroll
    for (int n = 0; n < 5; ++n) {
        if (warp < 4) {
            if (n < 4) produceA(n + 1, (n & 1) ? zs0 : zs1);
        } else {
            consumeB(n, (n & 1) ? zs1 : zs0);
        }
        __syncthreads();
    }

    // ---- covariance: 25 4x4-tiles x 8 t-slices (200 thr) + 20 means ----
    if (tid < 200) {
        const int tile = tid >> 3, slice = tid & 7;
        const int i0 = (tile / 5) * 4, j0 = (tile % 5) * 4;
        ull acc[16];
        #pragma unroll
        for (int e = 0; e < 16; ++e) acc[e] = 0;
        for (int t4 = slice; t4 < 64; t4 += 8) {
            ull ri[4][2], rj[4][2];
            #pragma unroll
            for (int a = 0; a < 4; ++a) {
                const ull* pi = (const ull*)&ys[(i0 + a) * YSS + 4 * t4];
                const ull* pj = (const ull*)&ys[(j0 + a) * YSS + 4 * t4];
                ri[a][0] = pi[0]; ri[a][1] = pi[1];
                rj[a][0] = pj[0]; rj[a][1] = pj[1];
            }
            #pragma unroll
            for (int a = 0; a < 4; ++a)
                #pragma unroll
                for (int d = 0; d < 4; ++d) {
                    fma2(acc[a * 4 + d], ri[a][0], rj[d][0]);
                    fma2(acc[a * 4 + d], ri[a][1], rj[d][1]);
                }
        }
        #pragma unroll
        for (int e = 0; e < 16; ++e) {
            float2 f = unpack2(acc[e]);
            red[tile * 128 + e * 8 + slice] = f.x + f.y;
        }
    } else if (tid < 240) {
        const int r = (tid - 200) >> 1, half = (tid - 200) & 1;
        const ull ones = pack2(1.f, 1.f);
        ull acc = 0;
        const ull* pr = (const ull*)&ys[r * YSS] + half * 64;
        const int n2 = half ? 61 : 64;
        for (int t2 = 0; t2 < n2; ++t2) fma2(acc, pr[t2], ones);
        float2 f = unpack2(acc);
        ys[r * YSS + 256 + half] = f.x + f.y;
    }
    __syncthreads();

    if (tid < 20)
        g_part[chunk][b][400 + tid] = ys[tid * YSS + 256] + ys[tid * YSS + 257];
    for (int p = tid; p < 400; p += 256) {
        int i = p / 20, j = p % 20;
        int tile = (i / 4) * 5 + (j / 4);
        int e = (i % 4) * 4 + (j % 4);
        const float* rp = &red[tile * 128 + e * 8];
        g_part[chunk][b][p] = ((rp[0] + rp[1]) + (rp[2] + rp[3]))
                            + ((rp[4] + rp[5]) + (rp[6] + rp[7]));
    }
}

// ---------------------------------------------------------------------------
// Eig: register-resident rows + shfl exchange. One warp per matrix.
// ---------------------------------------------------------------------------
__global__ void __launch_bounds__(32)
eig_kernel(const float* __restrict__ clf_w,
           const float* __restrict__ clf_b,
           float* __restrict__ out) {
    __shared__ float Ss[20][21];
    __shared__ float Us[20][21];
    __shared__ float m[20], lws[20];

    const int lane = threadIdx.x;
    const int b = blockIdx.x;
    const unsigned FULL = 0xffffffffu;

    if (lane < 20) {
        float acc = 0.f;
        #pragma unroll
        for (int ch = 0; ch < NCHUNK; ++ch) acc += g_part[ch][b][400 + lane];
        m[lane] = acc;
    }
    __syncwarp();
    for (int p = lane; p < 400; p += 32) {
        float acc = 0.f;
        #pragma unroll
        for (int ch = 0; ch < NCHUNK; ++ch) acc += g_part[ch][b][p];
        int i = p / 20, j = p % 20;
        Ss[i][j] = (acc - m[i] * m[j] * (1.0f / TT)) * (1.0f / (TT - 1));
    }
    __syncwarp();

    float Sr[20], Ur[20];
    #pragma unroll
    for (int j = 0; j < 20; ++j) {
        Sr[j] = (lane < 20) ? Ss[lane][j] : 0.f;
        Ur[j] = (lane == j) ? 1.f : 0.f;
    }

    for (int sweep = 0; sweep < NSWEEP; ++sweep) {
        #pragma unroll
        for (int r = 0; r < 19; ++r) {
            float app_r = 0.f, apq_r = 0.f, aqq_r = 0.f;
            #pragma unroll
            for (int i = 0; i < 10; ++i) {
                const int P = (i == 0) ? 0 : 1 + ((i - 1 + r) % 19);
                const int Q = 1 + ((18 - i + r) % 19);
                float app = __shfl_sync(FULL, Sr[P], P);
                float apq = __shfl_sync(FULL, Sr[Q], P);
                float aqq = __shfl_sync(FULL, Sr[Q], Q);
                if (lane == i) { app_r = app; apq_r = apq; aqq_r = aqq; }
            }
            float c_r = 1.f, s_r = 0.f;
            if (fabsf(apq_r) > 1e-12f) {
                float tau = __fdividef(aqq_r - app_r, 2.f * apq_r);
                float t = copysignf(__fdividef(1.f, fabsf(tau) + __fsqrt_rn(1.f + tau * tau)), tau);
                c_r = rsqrtf(1.f + t * t);
                s_r = t * c_r;
            }
            float cb[10], sb[10];
            #pragma unroll
            for (int i = 0; i < 10; ++i) {
                cb[i] = __shfl_sync(FULL, c_r, i);
                sb[i] = __shfl_sync(FULL, s_r, i);
            }
            #pragma unroll
            for (int i = 0; i < 10; ++i) {
                const int P = (i == 0) ? 0 : 1 + ((i - 1 + r) % 19);
                const int Q = 1 + ((18 - i + r) % 19);
                float sp = Sr[P], sq = Sr[Q];
                Sr[P] = cb[i] * sp - sb[i] * sq;
                Sr[Q] = sb[i] * sp + cb[i] * sq;
                float up = Ur[P], uq = Ur[Q];
                Ur[P] = cb[i] * up - sb[i] * uq;
                Ur[Q] = sb[i] * up + cb[i] * uq;
            }
            int partner, myi; bool isp;
            if (lane == 0)      { partner = 1 + ((18 + r) % 19); myi = 0; isp = true; }
            else if (lane < 20) {
                int v = (lane - 1 - r) % 19; if (v < 0) v += 19;
                if (v <= 8)       { partner = 1 + ((17 - v + r) % 19); myi = v + 1;  isp = true; }
                else if (v == 18) { partner = 0;                        myi = 0;      isp = false; }
                else              { partner = 1 + ((17 - v + r) % 19); myi = 18 - v; isp = false; }
            } else { partner = lane; myi = 0; isp = true; }
            float cc = __shfl_sync(FULL, c_r, myi);
            float ss = __shfl_sync(FULL, s_r, myi);
            float sg = isp ? -ss : ss;
            #pragma unroll
            for (int j = 0; j < 20; ++j) {
                float o = __shfl_sync(FULL, Sr[j], partner);
                Sr[j] = cc * Sr[j] + sg * o;
            }
        }
    }

    float d = 0.f;
    #pragma unroll
    for (int j = 0; j < 20; ++j) if (lane == j) d = Sr[j];
    if (lane < 20) {
        lws[lane] = logf(fmaxf(d, 1e-4f));
        #pragma unroll
        for (int j = 0; j < 20; ++j) Us[lane][j] = Ur[j];
    }
    __syncwarp();

    float o0 = 0.f, o1 = 0.f, o2 = 0.f, o3 = 0.f;
    const float SQ2 = 1.41421356237309515f;
    for (int p = lane; p < NPAIR; p += 32) {
        // closed-form decode of (i, j) from upper-triangular pair index
        int i = (int)((41.0f - sqrtf(1681.0f - 8.0f * (float)p)) * 0.5f);
        int off = (41 * i - i * i) >> 1;
        if (p < off) { --i; off = (41 * i - i * i) >> 1; }
        else {
            int off2 = (41 * (i + 1) - (i + 1) * (i + 1)) >> 1;
            if (p >= off2) { ++i; off = off2; }
        }
        int j = i + (p - off);
        float L = 0.f;
        #pragma unroll
        for (int mm = 0; mm < 20; ++mm) L += Us[i][mm] * lws[mm] * Us[j][mm];
        float z = L * ((i == j) ? 1.f : SQ2);
        o0 += z * clf_w[0 * NPAIR + p];
        o1 += z * clf_w[1 * NPAIR + p];
        o2 += z * clf_w[2 * NPAIR + p];
        o3 += z * clf_w[3 * NPAIR + p];
    }
    #pragma unroll
    for (int off = 16; off; off >>= 1) {
        o0 += __shfl_down_sync(FULL, o0, off);
        o1 += __shfl_down_sync(FULL, o1, off);
        o2 += __shfl_down_sync(FULL, o2, off);
        o3 += __shfl_down_sync(FULL, o3, off);
    }
    if (lane == 0) {
        out[b * 4 + 0] = o0 + clf_b[0];
        out[b * 4 + 1] = o1 + clf_b[1];
        out[b * 4 + 2] = o2 + clf_b[2];
        out[b * 4 + 3] = o3 + clf_b[3];
    }
}

// ---------------------------------------------------------------------------
extern "C" void kernel_launch(void* const* d_in, const int* in_sizes, int n_in,
                              void* d_out, int out_size) {
    const float* x       = (const float*)d_in[0];
    const float* conv1_w = (const float*)d_in[1];
    const float* conv2_w = (const float*)d_in[3];
    const float* W_bimap = (const float*)d_in[5];
    const float* clf_w   = (const float*)d_in[6];
    const float* clf_b   = (const float*)d_in[7];
    float* out = (float*)d_out;

    size_t smem_bytes = (size_t)(32 * ZW + 32 * ZW + 20 * YSS + 5120 + 224) * sizeof(float);
    cudaFuncSetAttribute(fused_kernel,
                         cudaFuncAttributeMaxDynamicSharedMemorySize,
                         (int)smem_bytes);

    prep_kernel<<<10, 256>>>(conv2_w, W_bimap);
    fused_kernel<<<dim3(NCHUNK, BB), 256, smem_bytes>>>(x, conv1_w);
    eig_kernel<<<BB, 32>>>(clf_w, clf_b, out);
}

// round 15
// speedup vs baseline: 1.1298x; 1.1298x over previous
#include <cuda_runtime.h>
#include <math.h>

#define BB 256
#define NCH 32
#define TT 2000
#define NTF 4
#define NSF 40
#define NSUB 20
#define TK 25
#define NPAIR 210
#define NCHUNK 8
#define TC 250
#define ZW 280
#define YSS 258
#define NSWEEP 5

typedef unsigned long long ull;

__device__ float g_W2T[32 * 80];               // [c*80 + sg]
__device__ float g_part[NCHUNK][BB][420];

__device__ __forceinline__ void fma2(ull& d, ull a, ull b) {
    asm("fma.rn.f32x2 %0, %1, %2, %0;" : "+l"(d) : "l"(a), "l"(b));
}
__device__ __forceinline__ ull pack2(float lo, float hi) {
    ull r; asm("mov.b64 %0, {%1, %2};" : "=l"(r) : "f"(lo), "f"(hi)); return r;
}
__device__ __forceinline__ float2 unpack2(ull v) {
    float2 f; asm("mov.b64 {%0, %1}, %2;" : "=f"(f.x), "=f"(f.y) : "l"(v)); return f;
}

// ---------------------------------------------------------------------------
__global__ void prep_kernel(const float* __restrict__ conv2_w,
                            const float* __restrict__ W_bimap) {
    int idx = blockIdx.x * blockDim.x + threadIdx.x;
    if (idx < 2560) {
        int c = idx / 80, sg = idx % 80;
        int s = sg / 4, g = sg % 4;
        float acc = 0.f;
        #pragma unroll 8
        for (int f = 0; f < NSF; ++f)
            acc += W_bimap[s * NSF + f] * conv2_w[f * 128 + g * 32 + c];
        g_W2T[c * 80 + sg] = acc;
    }
}

// ---------------------------------------------------------------------------
// Fused pipeline: warps 0-3 produce z slab n+1 (GEMM) while warps 4-7 consume
// slab n (temporal conv -> ys, zero-padding t>=250 inline). Then covariance.
// smem kept at 103.5 KB so 2 CTAs/SM (16 warps) stay resident.
// ---------------------------------------------------------------------------
__global__ void __launch_bounds__(256)
fused_kernel(const float* __restrict__ x, const float* __restrict__ w1) {
    extern __shared__ float smem[];
    float* xs  = smem;                  // 32*280 = 8960
    float* zs0 = xs + 32 * ZW;          // 4480
    float* zs1 = zs0 + 16 * ZW;         // 4480
    float* ys  = zs1 + 16 * ZW;         // 5160
    float* w2t = ys + 20 * YSS;         // 2560 (non-duplicated: keeps 2 CTAs/SM)
    float* w1p = w2t + 2560;            // 224
    float* red = zs0;                   // cov reduction aliases zs0

    const int tid = threadIdx.x;
    const int chunk = blockIdx.x, b = blockIdx.y;
    const int t0 = chunk * TC;
    const float* __restrict__ xb = x + (size_t)b * NCH * TT;

    for (int idx = tid; idx < 32 * ZW; idx += 256) {
        int c = idx / ZW, tt = idx % ZW;
        int gi = t0 - 12 + tt;
        if (gi < 0) gi = -gi;
        if (gi >= TT) gi = 2 * TT - 2 - gi;
        xs[c * ZW + tt] = xb[c * TT + gi];
    }
    for (int idx = tid; idx < 2560; idx += 256) w2t[idx] = g_W2T[idx];
    if (tid < 104) {
        int phase = tid / 52, rem = tid % 52, g = rem / 13, i = rem % 13;
        float lo, hi;
        if (phase == 0) {
            lo = w1[g * TK + 2 * i];
            hi = (i < 12) ? w1[g * TK + 2 * i + 1] : 0.f;
        } else {
            lo = (i == 0) ? 0.f : w1[g * TK + 2 * i - 1];
            hi = w1[g * TK + 2 * i];
        }
        int base = (phase * 4 + g) * 28 + 2 * i;
        w1p[base] = lo; w1p[base + 1] = hi;
    }
    if (tid >= 104 && tid < 120) {
        int s = tid - 104;
        w1p[(s >> 1) * 28 + 26 + (s & 1)] = 0.f;
    }
    __syncthreads();

    const int warp = tid >> 5, lane = tid & 31;
    const ull* wp = (const ull*)w1p;

    auto produceA = [&](int slb, float* zbuf) {
        if (lane >= 28) return;
        const int tau0 = lane * 10;
        const int sg0 = (slb * 4 + warp) * 4;
        ull acc[4][5];
        #pragma unroll
        for (int q = 0; q < 4; ++q)
            #pragma unroll
            for (int p = 0; p < 5; ++p) acc[q][p] = 0;

        #pragma unroll 2
        for (int c = 0; c < NCH; ++c) {
            const ull* xp = (const ull*)&xs[c * ZW + tau0];
            ull xv0 = xp[0], xv1 = xp[1], xv2 = xp[2], xv3 = xp[3], xv4 = xp[4];
            float4 wq = *(const float4*)&w2t[c * 80 + sg0];   // broadcast LDS.128
            ull wd0 = pack2(wq.x, wq.x), wd1 = pack2(wq.y, wq.y);
            ull wd2 = pack2(wq.z, wq.z), wd3 = pack2(wq.w, wq.w);
            fma2(acc[0][0], xv0, wd0); fma2(acc[0][1], xv1, wd0);
            fma2(acc[0][2], xv2, wd0); fma2(acc[0][3], xv3, wd0);
            fma2(acc[0][4], xv4, wd0);
            fma2(acc[1][0], xv0, wd1); fma2(acc[1][1], xv1, wd1);
            fma2(acc[1][2], xv2, wd1); fma2(acc[1][3], xv3, wd1);
            fma2(acc[1][4], xv4, wd1);
            fma2(acc[2][0], xv0, wd2); fma2(acc[2][1], xv1, wd2);
            fma2(acc[2][2], xv2, wd2); fma2(acc[2][3], xv3, wd2);
            fma2(acc[2][4], xv4, wd2);
            fma2(acc[3][0], xv0, wd3); fma2(acc[3][1], xv1, wd3);
            fma2(acc[3][2], xv2, wd3); fma2(acc[3][3], xv3, wd3);
            fma2(acc[3][4], xv4, wd3);
        }
        #pragma unroll
        for (int q = 0; q < 4; ++q) {
            ull* zr = (ull*)&zbuf[(warp * 4 + q) * ZW + tau0];
            #pragma unroll
            for (int p = 0; p < 5; ++p) zr[p] = acc[q][p];
        }
    };

    auto consumeB = [&](int slb, const float* zbuf) {
        const int s_loc = warp - 4;
        const int tl = lane * 8;
        ull accP[8];
        #pragma unroll
        for (int o = 0; o < 8; ++o) accP[o] = 0;

        #pragma unroll
        for (int g = 0; g < 4; ++g) {
            const ull* zrow = (const ull*)&zbuf[(s_loc * 4 + g) * ZW + tl];
            ull win[16];
            #pragma unroll
            for (int j = 0; j < 16; ++j) win[j] = zrow[j];
            #pragma unroll
            for (int i = 0; i < 13; ++i) {
                ull wa = wp[g * 14 + i], wb = wp[(4 + g) * 14 + i];
                #pragma unroll
                for (int m = 0; m < 4; ++m) {
                    fma2(accP[2 * m],     win[m + i], wa);
                    fma2(accP[2 * m + 1], win[m + i], wb);
                }
            }
        }
        const int s = slb * 4 + s_loc;
        // y for t >= TC zeroed inline; float2 stores (8B-aligned for all s)
        #pragma unroll
        for (int m = 0; m < 4; ++m) {
            float2 e = unpack2(accP[2 * m]);
            float2 o = unpack2(accP[2 * m + 1]);
            bool ok = (tl + 2 * m) < TC;
            float lo = ok ? (e.x + e.y) : 0.f;
            float hi = ok ? (o.x + o.y) : 0.f;
            *(float2*)&ys[s * YSS + tl + 2 * m] = make_float2(lo, hi);
        }
    };

    if (warp < 4) produceA(0, zs0);
    __syncthreads();
    #pragma unroll
    for (int n = 0; n < 5; ++n) {
        if (warp < 4) {
            if (n < 4) produceA(n + 1, (n & 1) ? zs0 : zs1);
        } else {
            consumeB(n, (n & 1) ? zs1 : zs0);
        }
        __syncthreads();
    }

    // ---- covariance: 25 4x4-tiles x 8 t-slices (200 thr) + 20 means ----
    if (tid < 200) {
        const int tile = tid >> 3, slice = tid & 7;
        const int i0 = (tile / 5) * 4, j0 = (tile % 5) * 4;
        ull acc[16];
        #pragma unroll
        for (int e = 0; e < 16; ++e) acc[e] = 0;
        for (int t4 = slice; t4 < 64; t4 += 8) {
            ull ri[4][2], rj[4][2];
            #pragma unroll
            for (int a = 0; a < 4; ++a) {
                const ull* pi = (const ull*)&ys[(i0 + a) * YSS + 4 * t4];
                const ull* pj = (const ull*)&ys[(j0 + a) * YSS + 4 * t4];
                ri[a][0] = pi[0]; ri[a][1] = pi[1];
                rj[a][0] = pj[0]; rj[a][1] = pj[1];
            }
            #pragma unroll
            for (int a = 0; a < 4; ++a)
                #pragma unroll
                for (int d = 0; d < 4; ++d) {
                    fma2(acc[a * 4 + d], ri[a][0], rj[d][0]);
                    fma2(acc[a * 4 + d], ri[a][1], rj[d][1]);
                }
        }
        #pragma unroll
        for (int e = 0; e < 16; ++e) {
            float2 f = unpack2(acc[e]);
            red[tile * 128 + e * 8 + slice] = f.x + f.y;
        }
    } else if (tid < 240) {
        const int r = (tid - 200) >> 1, half = (tid - 200) & 1;
        const ull ones = pack2(1.f, 1.f);
        ull acc = 0;
        const ull* pr = (const ull*)&ys[r * YSS] + half * 64;
        const int n2 = half ? 61 : 64;
        for (int t2 = 0; t2 < n2; ++t2) fma2(acc, pr[t2], ones);
        float2 f = unpack2(acc);
        ys[r * YSS + 256 + half] = f.x + f.y;
    }
    __syncthreads();

    if (tid < 20)
        g_part[chunk][b][400 + tid] = ys[tid * YSS + 256] + ys[tid * YSS + 257];
    for (int p = tid; p < 400; p += 256) {
        int i = p / 20, j = p % 20;
        int tile = (i / 4) * 5 + (j / 4);
        int e = (i % 4) * 4 + (j % 4);
        const float* rp = &red[tile * 128 + e * 8];
        g_part[chunk][b][p] = ((rp[0] + rp[1]) + (rp[2] + rp[3]))
                            + ((rp[4] + rp[5]) + (rp[6] + rp[7]));
    }
}

// ---------------------------------------------------------------------------
// Eig: register-resident rows + shfl exchange. One warp per matrix.
// ---------------------------------------------------------------------------
__global__ void __launch_bounds__(32)
eig_kernel(const float* __restrict__ clf_w,
           const float* __restrict__ clf_b,
           float* __restrict__ out) {
    __shared__ float Ss[20][21];
    __shared__ float Us[20][21];
    __shared__ float m[20], lws[20];

    const int lane = threadIdx.x;
    const int b = blockIdx.x;
    const unsigned FULL = 0xffffffffu;

    if (lane < 20) {
        float acc = 0.f;
        #pragma unroll
        for (int ch = 0; ch < NCHUNK; ++ch) acc += g_part[ch][b][400 + lane];
        m[lane] = acc;
    }
    __syncwarp();
    for (int p = lane; p < 400; p += 32) {
        float acc = 0.f;
        #pragma unroll
        for (int ch = 0; ch < NCHUNK; ++ch) acc += g_part[ch][b][p];
        int i = p / 20, j = p % 20;
        Ss[i][j] = (acc - m[i] * m[j] * (1.0f / TT)) * (1.0f / (TT - 1));
    }
    __syncwarp();

    float Sr[20], Ur[20];
    #pragma unroll
    for (int j = 0; j < 20; ++j) {
        Sr[j] = (lane < 20) ? Ss[lane][j] : 0.f;
        Ur[j] = (lane == j) ? 1.f : 0.f;
    }

    for (int sweep = 0; sweep < NSWEEP; ++sweep) {
        #pragma unroll
        for (int r = 0; r < 19; ++r) {
            float app_r = 0.f, apq_r = 0.f, aqq_r = 0.f;
            #pragma unroll
            for (int i = 0; i < 10; ++i) {
                const int P = (i == 0) ? 0 : 1 + ((i - 1 + r) % 19);
                const int Q = 1 + ((18 - i + r) % 19);
                float app = __shfl_sync(FULL, Sr[P], P);
                float apq = __shfl_sync(FULL, Sr[Q], P);
                float aqq = __shfl_sync(FULL, Sr[Q], Q);
                if (lane == i) { app_r = app; apq_r = apq; aqq_r = aqq; }
            }
            float c_r = 1.f, s_r = 0.f;
            if (fabsf(apq_r) > 1e-12f) {
                float tau = __fdividef(aqq_r - app_r, 2.f * apq_r);
                float t = copysignf(__fdividef(1.f, fabsf(tau) + __fsqrt_rn(1.f + tau * tau)), tau);
                c_r = rsqrtf(1.f + t * t);
                s_r = t * c_r;
            }
            float cb[10], sb[10];
            #pragma unroll
            for (int i = 0; i < 10; ++i) {
                cb[i] = __shfl_sync(FULL, c_r, i);
                sb[i] = __shfl_sync(FULL, s_r, i);
            }
            #pragma unroll
            for (int i = 0; i < 10; ++i) {
                const int P = (i == 0) ? 0 : 1 + ((i - 1 + r) % 19);
                const int Q = 1 + ((18 - i + r) % 19);
                float sp = Sr[P], sq = Sr[Q];
                Sr[P] = cb[i] * sp - sb[i] * sq;
                Sr[Q] = sb[i] * sp + cb[i] * sq;
                float up = Ur[P], uq = Ur[Q];
                Ur[P] = cb[i] * up - sb[i] * uq;
                Ur[Q] = sb[i] * up + cb[i] * uq;
            }
            int partner, myi; bool isp;
            if (lane == 0)      { partner = 1 + ((18 + r) % 19); myi = 0; isp = true; }
            else if (lane < 20) {
                int v = (lane - 1 - r) % 19; if (v < 0) v += 19;
                if (v <= 8)       { partner = 1 + ((17 - v + r) % 19); myi = v + 1;  isp = true; }
                else if (v == 18) { partner = 0;                        myi = 0;      isp = false; }
                else              { partner = 1 + ((17 - v + r) % 19); myi = 18 - v; isp = false; }
            } else { partner = lane; myi = 0; isp = true; }
            float cc = __shfl_sync(FULL, c_r, myi);
            float ss = __shfl_sync(FULL, s_r, myi);
            float sg = isp ? -ss : ss;
            #pragma unroll
            for (int j = 0; j < 20; ++j) {
                float o = __shfl_sync(FULL, Sr[j], partner);
                Sr[j] = cc * Sr[j] + sg * o;
            }
        }
    }

    float d = 0.f;
    #pragma unroll
    for (int j = 0; j < 20; ++j) if (lane == j) d = Sr[j];
    if (lane < 20) {
        lws[lane] = logf(fmaxf(d, 1e-4f));
        #pragma unroll
        for (int j = 0; j < 20; ++j) Us[lane][j] = Ur[j];
    }
    __syncwarp();

    float o0 = 0.f, o1 = 0.f, o2 = 0.f, o3 = 0.f;
    const float SQ2 = 1.41421356237309515f;
    for (int p = lane; p < NPAIR; p += 32) {
        // closed-form decode of (i, j) from upper-triangular pair index
        int i = (int)((41.0f - sqrtf(1681.0f - 8.0f * (float)p)) * 0.5f);
        int off = (41 * i - i * i) >> 1;
        if (p < off) { --i; off = (41 * i - i * i) >> 1; }
        else {
            int off2 = (41 * (i + 1) - (i + 1) * (i + 1)) >> 1;
            if (p >= off2) { ++i; off = off2; }
        }
        int j = i + (p - off);
        float L = 0.f;
        #pragma unroll
        for (int mm = 0; mm < 20; ++mm) L += Us[i][mm] * lws[mm] * Us[j][mm];
        float z = L * ((i == j) ? 1.f : SQ2);
        o0 += z * clf_w[0 * NPAIR + p];
        o1 += z * clf_w[1 * NPAIR + p];
        o2 += z * clf_w[2 * NPAIR + p];
        o3 += z * clf_w[3 * NPAIR + p];
    }
    #pragma unroll
    for (int off = 16; off; off >>= 1) {
        o0 += __shfl_down_sync(FULL, o0, off);
        o1 += __shfl_down_sync(FULL, o1, off);
        o2 += __shfl_down_sync(FULL, o2, off);
        o3 += __shfl_down_sync(FULL, o3, off);
    }
    if (lane == 0) {
        out[b * 4 + 0] = o0 + clf_b[0];
        out[b * 4 + 1] = o1 + clf_b[1];
        out[b * 4 + 2] = o2 + clf_b[2];
        out[b * 4 + 3] = o3 + clf_b[3];
    }
}

// ---------------------------------------------------------------------------
extern "C" void kernel_launch(void* const* d_in, const int* in_sizes, int n_in,
                              void* d_out, int out_size) {
    const float* x       = (const float*)d_in[0];
    const float* conv1_w = (const float*)d_in[1];
    const float* conv2_w = (const float*)d_in[3];
    const float* W_bimap = (const float*)d_in[5];
    const float* clf_w   = (const float*)d_in[6];
    const float* clf_b   = (const float*)d_in[7];
    float* out = (float*)d_out;

    size_t smem_bytes = (size_t)(32 * ZW + 32 * ZW + 20 * YSS + 2560 + 224) * sizeof(float);
    cudaFuncSetAttribute(fused_kernel,
                         cudaFuncAttributeMaxDynamicSharedMemorySize,
                         (int)smem_bytes);

    prep_kernel<<<10, 256>>>(conv2_w, W_bimap);
    fused_kernel<<<dim3(NCHUNK, BB), 256, smem_bytes>>>(x, conv1_w);
    eig_kernel<<<BB, 32>>>(clf_w, clf_b, out);
}

// round 16
// speedup vs baseline: 1.1489x; 1.0169x over previous
#include <cuda_runtime.h>
#include <math.h>

#define BB 256
#define NCH 32
#define TT 2000
#define NTF 4
#define NSF 40
#define NSUB 20
#define TK 25
#define NPAIR 210
#define NCHUNK 8
#define TC 250
#define ZW 280
#define YSS 258
#define NSWEEP 5

typedef unsigned long long ull;

__device__ float g_W2T[32 * 80];               // [c*80 + sg]
__device__ float g_part[NCHUNK][BB][420];

__device__ __forceinline__ void fma2(ull& d, ull a, ull b) {
    asm("fma.rn.f32x2 %0, %1, %2, %0;" : "+l"(d) : "l"(a), "l"(b));
}
__device__ __forceinline__ ull pack2(float lo, float hi) {
    ull r; asm("mov.b64 %0, {%1, %2};" : "=l"(r) : "f"(lo), "f"(hi)); return r;
}
__device__ __forceinline__ float2 unpack2(ull v) {
    float2 f; asm("mov.b64 {%0, %1}, %2;" : "=f"(f.x), "=f"(f.y) : "l"(v)); return f;
}
// balanced 10-way select by lane (valid for lane 0..9), depth-4 SEL tree
__device__ __forceinline__ float sel10(const float v[10], int lane) {
    float s0 = (lane & 1) ? v[1] : v[0];
    float s1 = (lane & 1) ? v[3] : v[2];
    float s2 = (lane & 1) ? v[5] : v[4];
    float s3 = (lane & 1) ? v[7] : v[6];
    float s4 = (lane & 1) ? v[9] : v[8];
    float t0 = (lane & 2) ? s1 : s0;
    float t1 = (lane & 2) ? s3 : s2;
    float u0 = (lane & 4) ? t1 : t0;
    return (lane & 8) ? s4 : u0;
}

// ---------------------------------------------------------------------------
__global__ void prep_kernel(const float* __restrict__ conv2_w,
                            const float* __restrict__ W_bimap) {
    int idx = blockIdx.x * blockDim.x + threadIdx.x;
    if (idx < 2560) {
        int c = idx / 80, sg = idx % 80;
        int s = sg / 4, g = sg % 4;
        float acc = 0.f;
        #pragma unroll 8
        for (int f = 0; f < NSF; ++f)
            acc += W_bimap[s * NSF + f] * conv2_w[f * 128 + g * 32 + c];
        g_W2T[c * 80 + sg] = acc;
    }
}

// ---------------------------------------------------------------------------
// Fused pipeline: warps 0-3 produce z slab n+1 (GEMM) while warps 4-7 consume
// slab n (temporal conv -> ys, inline zero-pad + row-mean reduction).
// Then tiled covariance. smem 103.5 KB -> 2 CTAs/SM (16 warps).
// ---------------------------------------------------------------------------
__global__ void __launch_bounds__(256)
fused_kernel(const float* __restrict__ x, const float* __restrict__ w1) {
    extern __shared__ float smem[];
    float* xs  = smem;                  // 32*280 = 8960
    float* zs0 = xs + 32 * ZW;          // 4480
    float* zs1 = zs0 + 16 * ZW;         // 4480
    float* ys  = zs1 + 16 * ZW;         // 5160
    float* w2t = ys + 20 * YSS;         // 2560
    float* w1p = w2t + 2560;            // 224
    float* red = zs0;                   // cov reduction aliases zs0

    const int tid = threadIdx.x;
    const int chunk = blockIdx.x, b = blockIdx.y;
    const int t0 = chunk * TC;
    const unsigned FULL = 0xffffffffu;
    const float* __restrict__ xb = x + (size_t)b * NCH * TT;

    for (int idx = tid; idx < 32 * ZW; idx += 256) {
        int c = idx / ZW, tt = idx % ZW;
        int gi = t0 - 12 + tt;
        if (gi < 0) gi = -gi;
        if (gi >= TT) gi = 2 * TT - 2 - gi;
        xs[c * ZW + tt] = xb[c * TT + gi];
    }
    for (int idx = tid; idx < 2560; idx += 256) w2t[idx] = g_W2T[idx];
    if (tid < 104) {
        int phase = tid / 52, rem = tid % 52, g = rem / 13, i = rem % 13;
        float lo, hi;
        if (phase == 0) {
            lo = w1[g * TK + 2 * i];
            hi = (i < 12) ? w1[g * TK + 2 * i + 1] : 0.f;
        } else {
            lo = (i == 0) ? 0.f : w1[g * TK + 2 * i - 1];
            hi = w1[g * TK + 2 * i];
        }
        int base = (phase * 4 + g) * 28 + 2 * i;
        w1p[base] = lo; w1p[base + 1] = hi;
    }
    if (tid >= 104 && tid < 120) {
        int s = tid - 104;
        w1p[(s >> 1) * 28 + 26 + (s & 1)] = 0.f;
    }
    __syncthreads();

    const int warp = tid >> 5, lane = tid & 31;
    const ull* wp = (const ull*)w1p;

    auto produceA = [&](int slb, float* zbuf) {
        if (lane >= 28) return;
        const int tau0 = lane * 10;
        const int sg0 = (slb * 4 + warp) * 4;
        ull acc[4][5];
        #pragma unroll
        for (int q = 0; q < 4; ++q)
            #pragma unroll
            for (int p = 0; p < 5; ++p) acc[q][p] = 0;

        #pragma unroll 2
        for (int c = 0; c < NCH; ++c) {
            const ull* xp = (const ull*)&xs[c * ZW + tau0];
            ull xv0 = xp[0], xv1 = xp[1], xv2 = xp[2], xv3 = xp[3], xv4 = xp[4];
            float4 wq = *(const float4*)&w2t[c * 80 + sg0];   // broadcast LDS.128
            ull wd0 = pack2(wq.x, wq.x), wd1 = pack2(wq.y, wq.y);
            ull wd2 = pack2(wq.z, wq.z), wd3 = pack2(wq.w, wq.w);
            fma2(acc[0][0], xv0, wd0); fma2(acc[0][1], xv1, wd0);
            fma2(acc[0][2], xv2, wd0); fma2(acc[0][3], xv3, wd0);
            fma2(acc[0][4], xv4, wd0);
            fma2(acc[1][0], xv0, wd1); fma2(acc[1][1], xv1, wd1);
            fma2(acc[1][2], xv2, wd1); fma2(acc[1][3], xv3, wd1);
            fma2(acc[1][4], xv4, wd1);
            fma2(acc[2][0], xv0, wd2); fma2(acc[2][1], xv1, wd2);
            fma2(acc[2][2], xv2, wd2); fma2(acc[2][3], xv3, wd2);
            fma2(acc[2][4], xv4, wd2);
            fma2(acc[3][0], xv0, wd3); fma2(acc[3][1], xv1, wd3);
            fma2(acc[3][2], xv2, wd3); fma2(acc[3][3], xv3, wd3);
            fma2(acc[3][4], xv4, wd3);
        }
        #pragma unroll
        for (int q = 0; q < 4; ++q) {
            ull* zr = (ull*)&zbuf[(warp * 4 + q) * ZW + tau0];
            #pragma unroll
            for (int p = 0; p < 5; ++p) zr[p] = acc[q][p];
        }
    };

    auto consumeB = [&](int slb, const float* zbuf) {
        const int s_loc = warp - 4;
        const int tl = lane * 8;
        ull accP[8];
        #pragma unroll
        for (int o = 0; o < 8; ++o) accP[o] = 0;

        #pragma unroll
        for (int g = 0; g < 4; ++g) {
            const ull* zrow = (const ull*)&zbuf[(s_loc * 4 + g) * ZW + tl];
            ull win[16];
            #pragma unroll
            for (int j = 0; j < 16; ++j) win[j] = zrow[j];
            #pragma unroll
            for (int i = 0; i < 13; ++i) {
                ull wa = wp[g * 14 + i], wb = wp[(4 + g) * 14 + i];
                #pragma unroll
                for (int m = 0; m < 4; ++m) {
                    fma2(accP[2 * m],     win[m + i], wa);
                    fma2(accP[2 * m + 1], win[m + i], wb);
                }
            }
        }
        const int s = slb * 4 + s_loc;
        float rs = 0.f;
        #pragma unroll
        for (int m = 0; m < 4; ++m) {
            float2 e = unpack2(accP[2 * m]);
            float2 o = unpack2(accP[2 * m + 1]);
            bool ok = (tl + 2 * m) < TC;
            float lo = ok ? (e.x + e.y) : 0.f;
            float hi = ok ? (o.x + o.y) : 0.f;
            rs += lo + hi;
            *(float2*)&ys[s * YSS + tl + 2 * m] = make_float2(lo, hi);
        }
        // row mean sum folded in (values already in registers)
        #pragma unroll
        for (int off = 16; off; off >>= 1) rs += __shfl_down_sync(FULL, rs, off);
        if (lane == 0) ys[s * YSS + 256] = rs;
    };

    if (warp < 4) produceA(0, zs0);
    __syncthreads();
    #pragma unroll
    for (int n = 0; n < 5; ++n) {
        if (warp < 4) {
            if (n < 4) produceA(n + 1, (n & 1) ? zs0 : zs1);
        } else {
            consumeB(n, (n & 1) ? zs1 : zs0);
        }
        __syncthreads();
    }

    // ---- covariance: 25 4x4-tiles x 8 t-slices (200 thr) ----
    if (tid < 200) {
        const int tile = tid >> 3, slice = tid & 7;
        const int i0 = (tile / 5) * 4, j0 = (tile % 5) * 4;
        ull acc[16];
        #pragma unroll
        for (int e = 0; e < 16; ++e) acc[e] = 0;
        for (int t4 = slice; t4 < 64; t4 += 8) {
            ull ri[4][2], rj[4][2];
            #pragma unroll
            for (int a = 0; a < 4; ++a) {
                const ull* pi = (const ull*)&ys[(i0 + a) * YSS + 4 * t4];
                const ull* pj = (const ull*)&ys[(j0 + a) * YSS + 4 * t4];
                ri[a][0] = pi[0]; ri[a][1] = pi[1];
                rj[a][0] = pj[0]; rj[a][1] = pj[1];
            }
            #pragma unroll
            for (int a = 0; a < 4; ++a)
                #pragma unroll
                for (int d = 0; d < 4; ++d) {
                    fma2(acc[a * 4 + d], ri[a][0], rj[d][0]);
                    fma2(acc[a * 4 + d], ri[a][1], rj[d][1]);
                }
        }
        #pragma unroll
        for (int e = 0; e < 16; ++e) {
            float2 f = unpack2(acc[e]);
            red[tile * 128 + e * 8 + slice] = f.x + f.y;
        }
    }
    __syncthreads();

    if (tid < 20)
        g_part[chunk][b][400 + tid] = ys[tid * YSS + 256];
    for (int p = tid; p < 400; p += 256) {
        int i = p / 20, j = p % 20;
        int tile = (i / 4) * 5 + (j / 4);
        int e = (i % 4) * 4 + (j % 4);
        const float* rp = &red[tile * 128 + e * 8];
        g_part[chunk][b][p] = ((rp[0] + rp[1]) + (rp[2] + rp[3]))
                            + ((rp[4] + rp[5]) + (rp[6] + rp[7]));
    }
}

// ---------------------------------------------------------------------------
// Eig: register-resident rows + shfl exchange. One warp per matrix.
// Gather via balanced SEL tree (breaks 10-deep predicated-select chain).
// ---------------------------------------------------------------------------
__global__ void __launch_bounds__(32)
eig_kernel(const float* __restrict__ clf_w,
           const float* __restrict__ clf_b,
           float* __restrict__ out) {
    __shared__ float Ss[20][21];
    __shared__ float Us[20][21];
    __shared__ float m[20], lws[20];

    const int lane = threadIdx.x;
    const int b = blockIdx.x;
    const unsigned FULL = 0xffffffffu;

    if (lane < 20) {
        float acc = 0.f;
        #pragma unroll
        for (int ch = 0; ch < NCHUNK; ++ch) acc += g_part[ch][b][400 + lane];
        m[lane] = acc;
    }
    __syncwarp();
    for (int p = lane; p < 400; p += 32) {
        float acc = 0.f;
        #pragma unroll
        for (int ch = 0; ch < NCHUNK; ++ch) acc += g_part[ch][b][p];
        int i = p / 20, j = p % 20;
        Ss[i][j] = (acc - m[i] * m[j] * (1.0f / TT)) * (1.0f / (TT - 1));
    }
    __syncwarp();

    float Sr[20], Ur[20];
    #pragma unroll
    for (int j = 0; j < 20; ++j) {
        Sr[j] = (lane < 20) ? Ss[lane][j] : 0.f;
        Ur[j] = (lane == j) ? 1.f : 0.f;
    }

    for (int sweep = 0; sweep < NSWEEP; ++sweep) {
        #pragma unroll
        for (int r = 0; r < 19; ++r) {
            // gather (app, apq, aqq) for all 10 pairs, then SEL-tree select
            float ac[10], pc[10], qc[10];
            #pragma unroll
            for (int i = 0; i < 10; ++i) {
                const int P = (i == 0) ? 0 : 1 + ((i - 1 + r) % 19);
                const int Q = 1 + ((18 - i + r) % 19);
                ac[i] = __shfl_sync(FULL, Sr[P], P);
                pc[i] = __shfl_sync(FULL, Sr[Q], P);
                qc[i] = __shfl_sync(FULL, Sr[Q], Q);
            }
            float app_r = sel10(ac, lane);
            float apq_r = sel10(pc, lane);
            float aqq_r = sel10(qc, lane);

            float c_r = 1.f, s_r = 0.f;
            if (fabsf(apq_r) > 1e-12f) {
                float tau = __fdividef(aqq_r - app_r, 2.f * apq_r);
                float t = copysignf(__fdividef(1.f, fabsf(tau) + __fsqrt_rn(1.f + tau * tau)), tau);
                c_r = rsqrtf(1.f + t * t);
                s_r = t * c_r;
            }
            float cb[10], sb[10];
            #pragma unroll
            for (int i = 0; i < 10; ++i) {
                cb[i] = __shfl_sync(FULL, c_r, i);
                sb[i] = __shfl_sync(FULL, s_r, i);
            }
            #pragma unroll
            for (int i = 0; i < 10; ++i) {
                const int P = (i == 0) ? 0 : 1 + ((i - 1 + r) % 19);
                const int Q = 1 + ((18 - i + r) % 19);
                float sp = Sr[P], sq = Sr[Q];
                Sr[P] = cb[i] * sp - sb[i] * sq;
                Sr[Q] = sb[i] * sp + cb[i] * sq;
                float up = Ur[P], uq = Ur[Q];
                Ur[P] = cb[i] * up - sb[i] * uq;
                Ur[Q] = sb[i] * up + cb[i] * uq;
            }
            int partner, myi; bool isp;
            if (lane == 0)      { partner = 1 + ((18 + r) % 19); myi = 0; isp = true; }
            else if (lane < 20) {
                int v = (lane - 1 - r) % 19; if (v < 0) v += 19;
                if (v <= 8)       { partner = 1 + ((17 - v + r) % 19); myi = v + 1;  isp = true; }
                else if (v == 18) { partner = 0;                        myi = 0;      isp = false; }
                else              { partner = 1 + ((17 - v + r) % 19); myi = 18 - v; isp = false; }
            } else { partner = lane; myi = 0; isp = true; }
            float cc = __shfl_sync(FULL, c_r, myi);
            float ss = __shfl_sync(FULL, s_r, myi);
            float sg = isp ? -ss : ss;
            #pragma unroll
            for (int j = 0; j < 20; ++j) {
                float o = __shfl_sync(FULL, Sr[j], partner);
                Sr[j] = cc * Sr[j] + sg * o;
            }
        }
    }

    float d = 0.f;
    #pragma unroll
    for (int j = 0; j < 20; ++j) if (lane == j) d = Sr[j];
    if (lane < 20) {
        lws[lane] = logf(fmaxf(d, 1e-4f));
        #pragma unroll
        for (int j = 0; j < 20; ++j) Us[lane][j] = Ur[j];
    }
    __syncwarp();

    float o0 = 0.f, o1 = 0.f, o2 = 0.f, o3 = 0.f;
    const float SQ2 = 1.41421356237309515f;
    for (int p = lane; p < NPAIR; p += 32) {
        int i = (int)((41.0f - sqrtf(1681.0f - 8.0f * (float)p)) * 0.5f);
        int off = (41 * i - i * i) >> 1;
        if (p < off) { --i; off = (41 * i - i * i) >> 1; }
        else {
            int off2 = (41 * (i + 1) - (i + 1) * (i + 1)) >> 1;
            if (p >= off2) { ++i; off = off2; }
        }
        int j = i + (p - off);
        float L = 0.f;
        #pragma unroll
        for (int mm = 0; mm < 20; ++mm) L += Us[i][mm] * lws[mm] * Us[j][mm];
        float z = L * ((i == j) ? 1.f : SQ2);
        o0 += z * clf_w[0 * NPAIR + p];
        o1 += z * clf_w[1 * NPAIR + p];
        o2 += z * clf_w[2 * NPAIR + p];
        o3 += z * clf_w[3 * NPAIR + p];
    }
    #pragma unroll
    for (int off = 16; off; off >>= 1) {
        o0 += __shfl_down_sync(FULL, o0, off);
        o1 += __shfl_down_sync(FULL, o1, off);
        o2 += __shfl_down_sync(FULL, o2, off);
        o3 += __shfl_down_sync(FULL, o3, off);
    }
    if (lane == 0) {
        out[b * 4 + 0] = o0 + clf_b[0];
        out[b * 4 + 1] = o1 + clf_b[1];
        out[b * 4 + 2] = o2 + clf_b[2];
        out[b * 4 + 3] = o3 + clf_b[3];
    }
}

// ---------------------------------------------------------------------------
extern "C" void kernel_launch(void* const* d_in, const int* in_sizes, int n_in,
                              void* d_out, int out_size) {
    const float* x       = (const float*)d_in[0];
    const float* conv1_w = (const float*)d_in[1];
    const float* conv2_w = (const float*)d_in[3];
    const float* W_bimap = (const float*)d_in[5];
    const float* clf_w   = (const float*)d_in[6];
    const float* clf_b   = (const float*)d_in[7];
    float* out = (float*)d_out;

    size_t smem_bytes = (size_t)(32 * ZW + 32 * ZW + 20 * YSS + 2560 + 224) * sizeof(float);
    cudaFuncSetAttribute(fused_kernel,
                         cudaFuncAttributeMaxDynamicSharedMemorySize,
                         (int)smem_bytes);

    prep_kernel<<<10, 256>>>(conv2_w, W_bimap);
    fused_kernel<<<dim3(NCHUNK, BB), 256, smem_bytes>>>(x, conv1_w);
    eig_kernel<<<BB, 32>>>(clf_w, clf_b, out);
}